// round 1
// baseline (speedup 1.0000x reference)
#include <cuda_runtime.h>
#include <math.h>

// Problem constants (fixed by the reference)
#define BB 2
#define SS 2048
#define TT (BB*SS)        // 4096 tokens
#define HH 2048
#define NHQ 16
#define NKV 8
#define HD 128
#define INTER 8192
#define EPS 1e-6f

// ---------------- scratch (allocation-free: __device__ globals) ----------------
__device__ float g_res1 [(size_t)TT*HH];
__device__ float g_xn   [(size_t)TT*HH];
__device__ float g_q    [(size_t)TT*NHQ*HD];
__device__ float g_k    [(size_t)TT*NKV*HD];
__device__ float g_v    [(size_t)TT*NKV*HD];
__device__ float g_attn [(size_t)TT*NHQ*HD];
__device__ float g_hattn[(size_t)TT*HH];
__device__ float g_h2   [(size_t)TT*HH];
__device__ float g_gu   [(size_t)TT*2*INTER];
__device__ float g_act  [(size_t)TT*INTER];
__device__ float g_invf [64];

// ---------------- fused add + RMSNorm ----------------
// res = a + b ; out = res * rsqrt(mean(res^2)+eps) * w
__global__ void add_rmsnorm_kernel(const float* __restrict__ a, const float* __restrict__ b,
                                   const float* __restrict__ w, float* __restrict__ res,
                                   float* __restrict__ out)
{
    int t = blockIdx.x, tid = threadIdx.x;
    const float4* a4 = (const float4*)(a + (size_t)t * HH);
    const float4* b4 = (const float4*)(b + (size_t)t * HH);
    float4* r4 = (float4*)(res + (size_t)t * HH);
    float4* o4 = (float4*)(out + (size_t)t * HH);
    const float4* w4 = (const float4*)w;

    float4 vv[2];
    float ss = 0.f;
#pragma unroll
    for (int ii = 0; ii < 2; ii++) {
        int idx = tid + ii * 256;
        float4 x = a4[idx], y = b4[idx];
        x.x += y.x; x.y += y.y; x.z += y.z; x.w += y.w;
        r4[idx] = x;
        vv[ii] = x;
        ss += x.x*x.x + x.y*x.y + x.z*x.z + x.w*x.w;
    }
#pragma unroll
    for (int off = 16; off; off >>= 1) ss += __shfl_xor_sync(0xffffffffu, ss, off);
    __shared__ float sh[8];
    __shared__ float s_inv;
    if ((tid & 31) == 0) sh[tid >> 5] = ss;
    __syncthreads();
    if (tid == 0) {
        float s = 0.f;
#pragma unroll
        for (int i = 0; i < 8; i++) s += sh[i];
        s_inv = rsqrtf(s / (float)HH + EPS);
    }
    __syncthreads();
    float inv = s_inv;
#pragma unroll
    for (int ii = 0; ii < 2; ii++) {
        int idx = tid + ii * 256;
        float4 x = vv[ii];
        float4 ww = w4[idx];
        float4 o = make_float4(x.x*inv*ww.x, x.y*inv*ww.y, x.z*inv*ww.z, x.w*inv*ww.w);
        o4[idx] = o;
    }
}

// ---------------- tiled fp32 GEMM: C[M,N] = A[M,K] @ B[K,N] (+ bias) ----------------
// BM=BN=128, BK=8, 256 threads, 8x8 micro-tile. All dims multiples of 128/8 here.
__global__ __launch_bounds__(256, 2) void gemm_tiled(
    const float* __restrict__ A, const float* __restrict__ Bm,
    const float* __restrict__ bias, float* __restrict__ C,
    int M, int N, int K)
{
    __shared__ float As[8][128];
    __shared__ float Bs[8][128];
    int tid = threadIdx.x;
    int bm = blockIdx.y * 128, bn = blockIdx.x * 128;
    int tx = tid & 15, ty = tid >> 4;
    int arow = tid >> 1, acol = (tid & 1) * 4;
    int brow = tid >> 5, bcol = (tid & 31) * 4;
    const float* Ap = A + (size_t)(bm + arow) * K + acol;
    const float* Bp = Bm + (size_t)brow * N + bn + bcol;

    float acc[8][8];
#pragma unroll
    for (int i = 0; i < 8; i++)
#pragma unroll
        for (int j = 0; j < 8; j++) acc[i][j] = 0.f;

    for (int k0 = 0; k0 < K; k0 += 8) {
        float4 av = *(const float4*)(Ap + k0);
        float4 bv = *(const float4*)(Bp + (size_t)k0 * N);
        __syncthreads();
        As[acol + 0][arow] = av.x;
        As[acol + 1][arow] = av.y;
        As[acol + 2][arow] = av.z;
        As[acol + 3][arow] = av.w;
        *(float4*)&Bs[brow][bcol] = bv;
        __syncthreads();
#pragma unroll
        for (int k = 0; k < 8; k++) {
            float4 a0 = *(const float4*)&As[k][ty * 8];
            float4 a1 = *(const float4*)&As[k][ty * 8 + 4];
            float4 b0 = *(const float4*)&Bs[k][tx * 8];
            float4 b1 = *(const float4*)&Bs[k][tx * 8 + 4];
            float a[8] = {a0.x,a0.y,a0.z,a0.w,a1.x,a1.y,a1.z,a1.w};
            float b[8] = {b0.x,b0.y,b0.z,b0.w,b1.x,b1.y,b1.z,b1.w};
#pragma unroll
            for (int i = 0; i < 8; i++)
#pragma unroll
                for (int j = 0; j < 8; j++) acc[i][j] += a[i] * b[j];
        }
    }

    float bfrag[8];
#pragma unroll
    for (int j = 0; j < 8; j++) bfrag[j] = bias ? bias[bn + tx * 8 + j] : 0.f;
#pragma unroll
    for (int i = 0; i < 8; i++) {
        float* Cp = C + (size_t)(bm + ty * 8 + i) * N + bn + tx * 8;
        float4 o0 = make_float4(acc[i][0]+bfrag[0], acc[i][1]+bfrag[1], acc[i][2]+bfrag[2], acc[i][3]+bfrag[3]);
        float4 o1 = make_float4(acc[i][4]+bfrag[4], acc[i][5]+bfrag[5], acc[i][6]+bfrag[6], acc[i][7]+bfrag[7]);
        *(float4*)Cp = o0;
        *(float4*)(Cp + 4) = o1;
    }
}

// ---------------- RoPE ----------------
__global__ void init_freq_kernel()
{
    int i = threadIdx.x;
    if (i < 64) g_invf[i] = (float)pow(1.0e6, -(double)i / 64.0);
}

__global__ void rope_kernel(float* __restrict__ q, float* __restrict__ k,
                            const int* __restrict__ pos)
{
    int idx = blockIdx.x * blockDim.x + threadIdx.x;
    // total = TT * (NHQ+NKV) * 64
    int i = idx & 63;
    int rest = idx >> 6;
    int head = rest % (NHQ + NKV);
    int t = rest / (NHQ + NKV);
    if (t >= TT) return;
    float* p;
    if (head < NHQ) p = q + ((size_t)t * NHQ + head) * HD;
    else            p = k + ((size_t)t * NKV + (head - NHQ)) * HD;
    float ang = (float)pos[t] * g_invf[i];
    float sv, cv;
    sincosf(ang, &sv, &cv);
    float x1 = p[i], x2 = p[i + 64];
    p[i]      = x1 * cv - x2 * sv;
    p[i + 64] = x2 * cv + x1 * sv;
}

// ---------------- causal flash attention (fp32, GQA rep=2) ----------------
// Tiles: 64 queries x 64 keys, HD=128. grid (32 qtiles, NH, B), 256 threads.
// smem: Qt[128][68], Kt[128][68], Vs[64][128], Pt[64][68]
#define QT_PITCH 68
#define FLASH_SMEM ((2 * 128 * QT_PITCH + 64 * 128 + 64 * QT_PITCH) * 4)

__global__ __launch_bounds__(256) void flash_kernel(
    const float* __restrict__ q, const float* __restrict__ k,
    const float* __restrict__ v, float* __restrict__ o)
{
    extern __shared__ float sm[];
    float* Qt = sm;                       // [128][68] transposed
    float* Kt = Qt + 128 * QT_PITCH;      // [128][68] transposed
    float* Vs = Kt + 128 * QT_PITCH;      // [64][128]
    float* Pt = Vs + 64 * 128;            // [64 keys][68] (transposed probs)

    int qt = blockIdx.x, h = blockIdx.y, b = blockIdx.z;
    int tid = threadIdx.x, tx = tid & 15, ty = tid >> 4;
    int qbase = qt * 64;
    int hk = h >> 1;   // GQA: rep = 2

    // load Q tile transposed
    for (int i = tid; i < 64 * 32; i += 256) {
        int r = i >> 5, c4 = (i & 31) * 4;
        float4 val = *(const float4*)(q + (((size_t)(b * SS + qbase + r) * NHQ + h) * HD + c4));
        Qt[(c4 + 0) * QT_PITCH + r] = val.x;
        Qt[(c4 + 1) * QT_PITCH + r] = val.y;
        Qt[(c4 + 2) * QT_PITCH + r] = val.z;
        Qt[(c4 + 3) * QT_PITCH + r] = val.w;
    }

    float m[4], l[4], accO[4][8];
#pragma unroll
    for (int i = 0; i < 4; i++) {
        m[i] = -1e30f; l[i] = 0.f;
#pragma unroll
        for (int c = 0; c < 8; c++) accO[i][c] = 0.f;
    }

    const float scale = 0.08838834764831845f;  // 1/sqrt(128)

    for (int kt = 0; kt <= qt; kt++) {
        int kbase = kt * 64;
        __syncthreads();   // previous PV done before overwriting K/V (also covers Q load on iter 0)
        for (int i = tid; i < 64 * 32; i += 256) {
            int r = i >> 5, c4 = (i & 31) * 4;
            size_t base = ((size_t)(b * SS + kbase + r) * NKV + hk) * HD + c4;
            float4 kv = *(const float4*)(k + base);
            Kt[(c4 + 0) * QT_PITCH + r] = kv.x;
            Kt[(c4 + 1) * QT_PITCH + r] = kv.y;
            Kt[(c4 + 2) * QT_PITCH + r] = kv.z;
            Kt[(c4 + 3) * QT_PITCH + r] = kv.w;
            float4 vv = *(const float4*)(v + base);
            *(float4*)&Vs[r * 128 + c4] = vv;
        }
        __syncthreads();

        // scores: 64x64x128
        float accS[4][4];
#pragma unroll
        for (int i = 0; i < 4; i++)
#pragma unroll
            for (int j = 0; j < 4; j++) accS[i][j] = 0.f;
#pragma unroll 8
        for (int d = 0; d < 128; d++) {
            float4 a = *(const float4*)&Qt[d * QT_PITCH + ty * 4];
            float4 bb = *(const float4*)&Kt[d * QT_PITCH + tx * 4];
            float av[4] = {a.x, a.y, a.z, a.w};
            float bv[4] = {bb.x, bb.y, bb.z, bb.w};
#pragma unroll
            for (int i = 0; i < 4; i++)
#pragma unroll
                for (int j = 0; j < 4; j++) accS[i][j] += av[i] * bv[j];
        }

        bool diag = (kt == qt);
#pragma unroll
        for (int i = 0; i < 4; i++) {
#pragma unroll
            for (int j = 0; j < 4; j++) {
                float s = accS[i][j] * scale;
                if (diag && (tx * 4 + j > ty * 4 + i)) s = -1e30f;
                accS[i][j] = s;
            }
            // online softmax per row
            float rm = fmaxf(fmaxf(accS[i][0], accS[i][1]), fmaxf(accS[i][2], accS[i][3]));
#pragma unroll
            for (int off = 8; off; off >>= 1) rm = fmaxf(rm, __shfl_xor_sync(0xffffffffu, rm, off));
            float mn = fmaxf(m[i], rm);
            float corr = __expf(m[i] - mn);
            float p[4], rs = 0.f;
#pragma unroll
            for (int j = 0; j < 4; j++) { p[j] = __expf(accS[i][j] - mn); rs += p[j]; }
#pragma unroll
            for (int off = 8; off; off >>= 1) rs += __shfl_xor_sync(0xffffffffu, rs, off);
            l[i] = l[i] * corr + rs;
            m[i] = mn;
#pragma unroll
            for (int c = 0; c < 8; c++) accO[i][c] *= corr;
#pragma unroll
            for (int j = 0; j < 4; j++) Pt[(tx * 4 + j) * QT_PITCH + ty * 4 + i] = p[j];
        }
        __syncthreads();

        // O += P @ V : 64x128x64
#pragma unroll 4
        for (int j = 0; j < 64; j++) {
            float4 p4 = *(const float4*)&Pt[j * QT_PITCH + ty * 4];
            float4 v0 = *(const float4*)&Vs[j * 128 + tx * 8];
            float4 v1 = *(const float4*)&Vs[j * 128 + tx * 8 + 4];
            float pp[4] = {p4.x, p4.y, p4.z, p4.w};
            float vv[8] = {v0.x, v0.y, v0.z, v0.w, v1.x, v1.y, v1.z, v1.w};
#pragma unroll
            for (int i = 0; i < 4; i++)
#pragma unroll
                for (int c = 0; c < 8; c++) accO[i][c] += pp[i] * vv[c];
        }
    }

#pragma unroll
    for (int i = 0; i < 4; i++) {
        float invl = 1.0f / l[i];
        int row = qbase + ty * 4 + i;
        float4 o0 = make_float4(accO[i][0]*invl, accO[i][1]*invl, accO[i][2]*invl, accO[i][3]*invl);
        float4 o1 = make_float4(accO[i][4]*invl, accO[i][5]*invl, accO[i][6]*invl, accO[i][7]*invl);
        float* op = o + (((size_t)(b * SS + row) * NHQ + h) * HD + tx * 8);
        *(float4*)op = o0;
        *(float4*)(op + 4) = o1;
    }
}

// ---------------- SiLU * up ----------------
__global__ void silu_mul_kernel(const float* __restrict__ gu, float* __restrict__ act)
{
    size_t idx = (size_t)blockIdx.x * blockDim.x + threadIdx.x;  // over TT*2048 float4
    size_t t = idx >> 11;
    size_t c = idx & 2047;
    const float4 g = *(const float4*)(gu + t * (2 * INTER) + c * 4);
    const float4 u = *(const float4*)(gu + t * (2 * INTER) + INTER + c * 4);
    float4 r;
    r.x = g.x / (1.f + __expf(-g.x)) * u.x;
    r.y = g.y / (1.f + __expf(-g.y)) * u.y;
    r.z = g.z / (1.f + __expf(-g.z)) * u.z;
    r.w = g.w / (1.f + __expf(-g.w)) * u.w;
    *(float4*)(act + t * INTER + c * 4) = r;
}

// ---------------- launch ----------------
extern "C" void kernel_launch(void* const* d_in, const int* in_sizes, int n_in,
                              void* d_out, int out_size)
{
    const int*   positions = (const int*)  d_in[0];
    const float* hidden    = (const float*)d_in[1];
    const float* residual  = (const float*)d_in[2];
    const float* ln1       = (const float*)d_in[3];
    const float* ln2       = (const float*)d_in[4];
    const float* wq        = (const float*)d_in[5];
    const float* bq        = (const float*)d_in[6];
    const float* wk        = (const float*)d_in[7];
    const float* bk        = (const float*)d_in[8];
    const float* wv        = (const float*)d_in[9];
    const float* bv        = (const float*)d_in[10];
    const float* wo        = (const float*)d_in[11];
    const float* wgu       = (const float*)d_in[12];
    const float* wd        = (const float*)d_in[13];

    float* out_h   = (float*)d_out;
    float* out_res = out_h + (size_t)out_size / 2;

    float *res1, *xn, *q, *k, *v, *attn, *hattn, *h2, *gu, *act;
    cudaGetSymbolAddress((void**)&res1,  g_res1);
    cudaGetSymbolAddress((void**)&xn,    g_xn);
    cudaGetSymbolAddress((void**)&q,     g_q);
    cudaGetSymbolAddress((void**)&k,     g_k);
    cudaGetSymbolAddress((void**)&v,     g_v);
    cudaGetSymbolAddress((void**)&attn,  g_attn);
    cudaGetSymbolAddress((void**)&hattn, g_hattn);
    cudaGetSymbolAddress((void**)&h2,    g_h2);
    cudaGetSymbolAddress((void**)&gu,    g_gu);
    cudaGetSymbolAddress((void**)&act,   g_act);

    // 1. res1 = hidden + residual ; xn = rmsnorm(res1)*ln1
    add_rmsnorm_kernel<<<TT, 256>>>(hidden, residual, ln1, res1, xn);

    // 2. QKV projections (with bias)
    gemm_tiled<<<dim3(HH / 128, TT / 128), 256>>>(xn, wq, bq, q, TT, NHQ * HD, HH);
    gemm_tiled<<<dim3((NKV * HD) / 128, TT / 128), 256>>>(xn, wk, bk, k, TT, NKV * HD, HH);
    gemm_tiled<<<dim3((NKV * HD) / 128, TT / 128), 256>>>(xn, wv, bv, v, TT, NKV * HD, HH);

    // 3. RoPE
    init_freq_kernel<<<1, 64>>>();
    {
        int total = TT * (NHQ + NKV) * 64;
        rope_kernel<<<(total + 255) / 256, 256>>>(q, k, positions);
    }

    // 4. causal flash attention
    cudaFuncSetAttribute(flash_kernel, cudaFuncAttributeMaxDynamicSharedMemorySize, FLASH_SMEM);
    flash_kernel<<<dim3(SS / 64, NHQ, BB), 256, FLASH_SMEM>>>(q, k, v, attn);

    // 5. output projection
    gemm_tiled<<<dim3(HH / 128, TT / 128), 256>>>(attn, wo, nullptr, hattn, TT, HH, NHQ * HD);

    // 6. res2 = hattn + res1 (-> out second half) ; h2 = rmsnorm(res2)*ln2
    add_rmsnorm_kernel<<<TT, 256>>>(hattn, res1, ln2, out_res, h2);

    // 7. gate_up GEMM
    gemm_tiled<<<dim3((2 * INTER) / 128, TT / 128), 256>>>(h2, wgu, nullptr, gu, TT, 2 * INTER, HH);

    // 8. SiLU * up
    {
        size_t total4 = (size_t)TT * (INTER / 4);
        silu_mul_kernel<<<(unsigned)(total4 / 256), 256>>>(gu, act);
    }

    // 9. down GEMM -> out first half
    gemm_tiled<<<dim3(HH / 128, TT / 128), 256>>>(act, wd, nullptr, out_h, TT, HH, INTER);
}

// round 3
// speedup vs baseline: 2.2843x; 2.2843x over previous
#include <cuda_runtime.h>
#include <cuda_bf16.h>
#include <cstdint>
#include <math.h>

// Problem constants
#define BB 2
#define SS 2048
#define TT (BB*SS)        // 4096 tokens
#define HH 2048
#define NHQ 16
#define NKV 8
#define HD 128
#define INTER 8192
#define EPS 1e-6f

// ======================= scratch (__device__ globals) =======================
__device__ __align__(256) float g_res1 [(size_t)TT*HH];
__device__ __align__(256) float g_q    [(size_t)TT*NHQ*HD];
__device__ __align__(256) float g_k    [(size_t)TT*NKV*HD];
__device__ __align__(256) float g_v    [(size_t)TT*NKV*HD];
__device__ __align__(256) float g_hattn[(size_t)TT*HH];
__device__ __align__(256) float g_gu   [(size_t)TT*2*INTER];
__device__ float g_invf [64];

// bf16 split activations
__device__ __align__(256) __nv_bfloat16 g_xn_h [(size_t)TT*HH];
__device__ __align__(256) __nv_bfloat16 g_xn_l [(size_t)TT*HH];
__device__ __align__(256) __nv_bfloat16 g_at_h [(size_t)TT*HH];
__device__ __align__(256) __nv_bfloat16 g_at_l [(size_t)TT*HH];
__device__ __align__(256) __nv_bfloat16 g_h2_h [(size_t)TT*HH];
__device__ __align__(256) __nv_bfloat16 g_h2_l [(size_t)TT*HH];
__device__ __align__(256) __nv_bfloat16 g_ac_h [(size_t)TT*INTER];
__device__ __align__(256) __nv_bfloat16 g_ac_l [(size_t)TT*INTER];

// bf16 split transposed weights [N, K]
__device__ __align__(256) __nv_bfloat16 g_wqT_h[(size_t)(NHQ*HD)*HH];
__device__ __align__(256) __nv_bfloat16 g_wqT_l[(size_t)(NHQ*HD)*HH];
__device__ __align__(256) __nv_bfloat16 g_wkT_h[(size_t)(NKV*HD)*HH];
__device__ __align__(256) __nv_bfloat16 g_wkT_l[(size_t)(NKV*HD)*HH];
__device__ __align__(256) __nv_bfloat16 g_wvT_h[(size_t)(NKV*HD)*HH];
__device__ __align__(256) __nv_bfloat16 g_wvT_l[(size_t)(NKV*HD)*HH];
__device__ __align__(256) __nv_bfloat16 g_woT_h[(size_t)HH*(NHQ*HD)];
__device__ __align__(256) __nv_bfloat16 g_woT_l[(size_t)HH*(NHQ*HD)];
__device__ __align__(256) __nv_bfloat16 g_guT_h[(size_t)(2*INTER)*HH];
__device__ __align__(256) __nv_bfloat16 g_guT_l[(size_t)(2*INTER)*HH];
__device__ __align__(256) __nv_bfloat16 g_wdT_h[(size_t)HH*INTER];
__device__ __align__(256) __nv_bfloat16 g_wdT_l[(size_t)HH*INTER];

// ======================= PTX helpers (baseline sm_80/90 features only) =======================
__device__ __forceinline__ uint32_t s2u(const void* p) {
    uint32_t a;
    asm("{ .reg .u64 t; cvta.to.shared.u64 t, %1; cvt.u32.u64 %0, t; }" : "=r"(a) : "l"(p));
    return a;
}
__device__ __forceinline__ void cpasync16(uint32_t dst, const void* src) {
    asm volatile("cp.async.cg.shared.global [%0], [%1], 16;" :: "r"(dst), "l"(src) : "memory");
}
__device__ __forceinline__ void cp_commit() {
    asm volatile("cp.async.commit_group;" ::: "memory");
}
template<int N_>
__device__ __forceinline__ void cp_wait() {
    asm volatile("cp.async.wait_group %0;" :: "n"(N_) : "memory");
}
__device__ __forceinline__ void ldsm4(uint32_t* r, uint32_t addr) {
    asm volatile("ldmatrix.sync.aligned.m8n8.x4.shared.b16 {%0,%1,%2,%3}, [%4];"
                 : "=r"(r[0]), "=r"(r[1]), "=r"(r[2]), "=r"(r[3]) : "r"(addr));
}
__device__ __forceinline__ void mma_bf16(float* d, const uint32_t* a, const uint32_t* b) {
    asm volatile(
        "mma.sync.aligned.m16n8k16.row.col.f32.bf16.bf16.f32 "
        "{%0,%1,%2,%3}, {%4,%5,%6,%7}, {%8,%9}, {%0,%1,%2,%3};"
        : "+f"(d[0]), "+f"(d[1]), "+f"(d[2]), "+f"(d[3])
        : "r"(a[0]), "r"(a[1]), "r"(a[2]), "r"(a[3]), "r"(b[0]), "r"(b[1]));
}

// ======================= bf16 split helpers =======================
__device__ __forceinline__ void split_store2(float x, float y,
                                             __nv_bfloat162* ph, __nv_bfloat162* pl)
{
    __nv_bfloat16 hx = __float2bfloat16(x), hy = __float2bfloat16(y);
    *ph = __halves2bfloat162(hx, hy);
    *pl = __halves2bfloat162(__float2bfloat16(x - __bfloat162float(hx)),
                             __float2bfloat16(y - __bfloat162float(hy)));
}

// ======================= fused add + RMSNorm (bf16-split output) =======================
__global__ void add_rmsnorm_kernel(const float* __restrict__ a, const float* __restrict__ b,
                                   const float* __restrict__ w, float* __restrict__ res,
                                   __nv_bfloat16* __restrict__ oh, __nv_bfloat16* __restrict__ ol)
{
    int t = blockIdx.x, tid = threadIdx.x;
    const float4* a4 = (const float4*)(a + (size_t)t * HH);
    const float4* b4 = (const float4*)(b + (size_t)t * HH);
    float4* r4 = (float4*)(res + (size_t)t * HH);
    const float4* w4 = (const float4*)w;
    __nv_bfloat162* oh2 = (__nv_bfloat162*)(oh + (size_t)t * HH);
    __nv_bfloat162* ol2 = (__nv_bfloat162*)(ol + (size_t)t * HH);

    float4 vv[2];
    float ss = 0.f;
#pragma unroll
    for (int ii = 0; ii < 2; ii++) {
        int idx = tid + ii * 256;
        float4 x = a4[idx], y = b4[idx];
        x.x += y.x; x.y += y.y; x.z += y.z; x.w += y.w;
        r4[idx] = x;
        vv[ii] = x;
        ss += x.x*x.x + x.y*x.y + x.z*x.z + x.w*x.w;
    }
#pragma unroll
    for (int off = 16; off; off >>= 1) ss += __shfl_xor_sync(0xffffffffu, ss, off);
    __shared__ float sh[8];
    __shared__ float s_inv;
    if ((tid & 31) == 0) sh[tid >> 5] = ss;
    __syncthreads();
    if (tid == 0) {
        float s = 0.f;
#pragma unroll
        for (int i = 0; i < 8; i++) s += sh[i];
        s_inv = rsqrtf(s / (float)HH + EPS);
    }
    __syncthreads();
    float inv = s_inv;
#pragma unroll
    for (int ii = 0; ii < 2; ii++) {
        int idx = tid + ii * 256;
        float4 x = vv[ii];
        float4 ww = w4[idx];
        float o0 = x.x*inv*ww.x, o1 = x.y*inv*ww.y, o2 = x.z*inv*ww.z, o3 = x.w*inv*ww.w;
        __nv_bfloat162 h0, l0, h1, l1;
        split_store2(o0, o1, &h0, &l0);
        split_store2(o2, o3, &h1, &l1);
        oh2[idx*2]   = h0; oh2[idx*2+1] = h1;
        ol2[idx*2]   = l0; ol2[idx*2+1] = l1;
    }
}

// ======================= weight transpose + split: W[K,N] -> T_hi/T_lo [N,K] =======================
__global__ void wsplit_kernel(const float* __restrict__ W,
                              __nv_bfloat16* __restrict__ Th, __nv_bfloat16* __restrict__ Tl,
                              int K, int N)
{
    __shared__ float tile[32][33];
    int k0 = blockIdx.y * 32, n0 = blockIdx.x * 32;
    int tx = threadIdx.x, ty = threadIdx.y;
#pragma unroll
    for (int j = 0; j < 4; j++)
        tile[ty + 8*j][tx] = W[(size_t)(k0 + ty + 8*j) * N + n0 + tx];
    __syncthreads();
#pragma unroll
    for (int j = 0; j < 4; j++) {
        int n = ty + 8*j;
        float v = tile[tx][n];
        __nv_bfloat16 h = __float2bfloat16(v);
        float lo = v - __bfloat162float(h);
        Th[(size_t)(n0 + n) * K + k0 + tx] = h;
        Tl[(size_t)(n0 + n) * K + k0 + tx] = __float2bfloat16(lo);
    }
}

// ======================= mma.sync bf16-split GEMM =======================
// C[M,N] = Ah@BhT + Ah@BlT + Al@BhT (+bias). A[M,K] bf16 pair, B[N,K] bf16 pair.
// CTA: 128x128, BK=32 (two k16 steps), 256 threads = 2(M) x 4(N) warps, warp tile 64x32.
#define SO_AH 0
#define SO_AL 8192
#define SO_BH 16384
#define SO_BL 24576
#define STAGE_STRIDE 32768
#define GEMM_SMEM 65536
// swizzled 16B-unit offset within a [128 rows][32 halves] tile
__device__ __forceinline__ uint32_t soff(int row, int u) {
    return (uint32_t)(row * 64 + ((u ^ ((row >> 1) & 3)) << 4));
}

__global__ __launch_bounds__(256, 1) void gemm_mma(
    const __nv_bfloat16* __restrict__ Ah, const __nv_bfloat16* __restrict__ Al,
    const __nv_bfloat16* __restrict__ Bh, const __nv_bfloat16* __restrict__ Bl,
    const float* __restrict__ bias, float* __restrict__ C, int M, int N, int K)
{
    extern __shared__ char smc[];
    uint32_t sb = s2u(smc);
    int tid = threadIdx.x, lane = tid & 31, wid = tid >> 5;
    int wm = wid >> 2, wn = wid & 3;
    int m0 = blockIdx.y * 128, n0 = blockIdx.x * 128;

    float acc[4][4][4];
#pragma unroll
    for (int i = 0; i < 4; i++)
#pragma unroll
        for (int j = 0; j < 4; j++)
#pragma unroll
            for (int c = 0; c < 4; c++) acc[i][j][c] = 0.f;

    // loader: 512 16B-chunks per tile / 256 threads = 2 rows per thread (row, row+64)
    int lrow = tid >> 2, lu = tid & 3;
    uint32_t ls0 = soff(lrow, lu), ls1 = soff(lrow + 64, lu);
    size_t gaoff0 = (size_t)(m0 + lrow) * K + lu * 8;
    size_t gaoff1 = (size_t)(m0 + lrow + 64) * K + lu * 8;
    size_t gboff0 = (size_t)(n0 + lrow) * K + lu * 8;
    size_t gboff1 = (size_t)(n0 + lrow + 64) * K + lu * 8;

    // fragment lane mappings
    int rA = lane & 15, uA = lane >> 4;                 // A ldmatrix.x4
    int rB = (lane & 7) | ((lane & 16) >> 1);           // B ldmatrix.x4
    int uB = (lane >> 3) & 1;

    int nIter = K / 32;

    // prologue: stage 0
    {
        uint32_t s = sb;
        cpasync16(s + SO_AH + ls0, Ah + gaoff0);
        cpasync16(s + SO_AH + ls1, Ah + gaoff1);
        cpasync16(s + SO_AL + ls0, Al + gaoff0);
        cpasync16(s + SO_AL + ls1, Al + gaoff1);
        cpasync16(s + SO_BH + ls0, Bh + gboff0);
        cpasync16(s + SO_BH + ls1, Bh + gboff1);
        cpasync16(s + SO_BL + ls0, Bl + gboff0);
        cpasync16(s + SO_BL + ls1, Bl + gboff1);
        cp_commit();
    }

    for (int it = 0; it < nIter; it++) {
        if (it + 1 < nIter) {
            uint32_t s = sb + ((it + 1) & 1) * STAGE_STRIDE;
            size_t ko = (size_t)(it + 1) * 32;
            cpasync16(s + SO_AH + ls0, Ah + gaoff0 + ko);
            cpasync16(s + SO_AH + ls1, Ah + gaoff1 + ko);
            cpasync16(s + SO_AL + ls0, Al + gaoff0 + ko);
            cpasync16(s + SO_AL + ls1, Al + gaoff1 + ko);
            cpasync16(s + SO_BH + ls0, Bh + gboff0 + ko);
            cpasync16(s + SO_BH + ls1, Bh + gboff1 + ko);
            cpasync16(s + SO_BL + ls0, Bl + gboff0 + ko);
            cpasync16(s + SO_BL + ls1, Bl + gboff1 + ko);
            cp_commit();
            cp_wait<1>();
        } else {
            cp_wait<0>();
        }
        __syncthreads();

        uint32_t s = sb + (it & 1) * STAGE_STRIDE;
#pragma unroll
        for (int ks = 0; ks < 2; ks++) {
            uint32_t ah[4][4], al[4][4], bh[4][2], bl[4][2];
#pragma unroll
            for (int mt = 0; mt < 4; mt++) {
                uint32_t off = soff(wm * 64 + mt * 16 + rA, ks * 2 + uA);
                ldsm4(ah[mt], s + SO_AH + off);
                ldsm4(al[mt], s + SO_AL + off);
            }
#pragma unroll
            for (int nt = 0; nt < 2; nt++) {
                uint32_t off = soff(wn * 32 + nt * 16 + rB, ks * 2 + uB);
                uint32_t t4[4];
                ldsm4(t4, s + SO_BH + off);
                bh[nt*2][0] = t4[0]; bh[nt*2][1] = t4[1];
                bh[nt*2+1][0] = t4[2]; bh[nt*2+1][1] = t4[3];
                ldsm4(t4, s + SO_BL + off);
                bl[nt*2][0] = t4[0]; bl[nt*2][1] = t4[1];
                bl[nt*2+1][0] = t4[2]; bl[nt*2+1][1] = t4[3];
            }
#pragma unroll
            for (int mt = 0; mt < 4; mt++)
#pragma unroll
                for (int nf = 0; nf < 4; nf++) {
                    mma_bf16(acc[mt][nf], ah[mt], bh[nf]);
                    mma_bf16(acc[mt][nf], ah[mt], bl[nf]);
                    mma_bf16(acc[mt][nf], al[mt], bh[nf]);
                }
        }
        __syncthreads();
    }

    // epilogue
    int crow = lane >> 2, ccol = (lane & 3) * 2;
#pragma unroll
    for (int mt = 0; mt < 4; mt++) {
#pragma unroll
        for (int nf = 0; nf < 4; nf++) {
            int r = m0 + wm * 64 + mt * 16 + crow;
            int cidx = n0 + wn * 32 + nf * 8 + ccol;
            float b0 = 0.f, b1 = 0.f;
            if (bias) { b0 = bias[cidx]; b1 = bias[cidx + 1]; }
            float2 v0 = make_float2(acc[mt][nf][0] + b0, acc[mt][nf][1] + b1);
            float2 v1 = make_float2(acc[mt][nf][2] + b0, acc[mt][nf][3] + b1);
            *(float2*)(C + (size_t)r * N + cidx) = v0;
            *(float2*)(C + (size_t)(r + 8) * N + cidx) = v1;
        }
    }
}

// ======================= RoPE =======================
__global__ void init_freq_kernel()
{
    int i = threadIdx.x;
    if (i < 64) g_invf[i] = (float)pow(1.0e6, -(double)i / 64.0);
}

__global__ void rope_kernel(float* __restrict__ q, float* __restrict__ k,
                            const int* __restrict__ pos)
{
    int idx = blockIdx.x * blockDim.x + threadIdx.x;
    int i = idx & 63;
    int rest = idx >> 6;
    int head = rest % (NHQ + NKV);
    int t = rest / (NHQ + NKV);
    if (t >= TT) return;
    float* p;
    if (head < NHQ) p = q + ((size_t)t * NHQ + head) * HD;
    else            p = k + ((size_t)t * NKV + (head - NHQ)) * HD;
    float ang = (float)pos[t] * g_invf[i];
    float sv, cv;
    sincosf(ang, &sv, &cv);
    float x1 = p[i], x2 = p[i + 64];
    p[i]      = x1 * cv - x2 * sv;
    p[i + 64] = x2 * cv + x1 * sv;
}

// ======================= causal flash attention (fp32, GQA rep=2) =======================
#define QT_PITCH 68
#define FLASH_SMEM ((2 * 128 * QT_PITCH + 64 * 128 + 64 * QT_PITCH) * 4)

__global__ __launch_bounds__(256) void flash_kernel(
    const float* __restrict__ q, const float* __restrict__ k,
    const float* __restrict__ v,
    __nv_bfloat16* __restrict__ oh, __nv_bfloat16* __restrict__ ol)
{
    extern __shared__ float smf[];
    float* Qt = smf;
    float* Kt = Qt + 128 * QT_PITCH;
    float* Vs = Kt + 128 * QT_PITCH;
    float* Pt = Vs + 64 * 128;

    int qt = blockIdx.x, h = blockIdx.y, b = blockIdx.z;
    int tid = threadIdx.x, tx = tid & 15, ty = tid >> 4;
    int qbase = qt * 64;
    int hk = h >> 1;

    for (int i = tid; i < 64 * 32; i += 256) {
        int r = i >> 5, c4 = (i & 31) * 4;
        float4 val = *(const float4*)(q + (((size_t)(b * SS + qbase + r) * NHQ + h) * HD + c4));
        Qt[(c4 + 0) * QT_PITCH + r] = val.x;
        Qt[(c4 + 1) * QT_PITCH + r] = val.y;
        Qt[(c4 + 2) * QT_PITCH + r] = val.z;
        Qt[(c4 + 3) * QT_PITCH + r] = val.w;
    }

    float m[4], l[4], accO[4][8];
#pragma unroll
    for (int i = 0; i < 4; i++) {
        m[i] = -1e30f; l[i] = 0.f;
#pragma unroll
        for (int c = 0; c < 8; c++) accO[i][c] = 0.f;
    }

    const float scale = 0.08838834764831845f;

    for (int kt = 0; kt <= qt; kt++) {
        int kbase = kt * 64;
        __syncthreads();
        for (int i = tid; i < 64 * 32; i += 256) {
            int r = i >> 5, c4 = (i & 31) * 4;
            size_t base = ((size_t)(b * SS + kbase + r) * NKV + hk) * HD + c4;
            float4 kv = *(const float4*)(k + base);
            Kt[(c4 + 0) * QT_PITCH + r] = kv.x;
            Kt[(c4 + 1) * QT_PITCH + r] = kv.y;
            Kt[(c4 + 2) * QT_PITCH + r] = kv.z;
            Kt[(c4 + 3) * QT_PITCH + r] = kv.w;
            float4 vv = *(const float4*)(v + base);
            *(float4*)&Vs[r * 128 + c4] = vv;
        }
        __syncthreads();

        float accS[4][4];
#pragma unroll
        for (int i = 0; i < 4; i++)
#pragma unroll
            for (int j = 0; j < 4; j++) accS[i][j] = 0.f;
#pragma unroll 8
        for (int d = 0; d < 128; d++) {
            float4 a = *(const float4*)&Qt[d * QT_PITCH + ty * 4];
            float4 bb = *(const float4*)&Kt[d * QT_PITCH + tx * 4];
            float av[4] = {a.x, a.y, a.z, a.w};
            float bv[4] = {bb.x, bb.y, bb.z, bb.w};
#pragma unroll
            for (int i = 0; i < 4; i++)
#pragma unroll
                for (int j = 0; j < 4; j++) accS[i][j] += av[i] * bv[j];
        }

        bool diag = (kt == qt);
#pragma unroll
        for (int i = 0; i < 4; i++) {
#pragma unroll
            for (int j = 0; j < 4; j++) {
                float s = accS[i][j] * scale;
                if (diag && (tx * 4 + j > ty * 4 + i)) s = -1e30f;
                accS[i][j] = s;
            }
            float rm = fmaxf(fmaxf(accS[i][0], accS[i][1]), fmaxf(accS[i][2], accS[i][3]));
#pragma unroll
            for (int off = 8; off; off >>= 1) rm = fmaxf(rm, __shfl_xor_sync(0xffffffffu, rm, off));
            float mn = fmaxf(m[i], rm);
            float corr = __expf(m[i] - mn);
            float p[4], rs = 0.f;
#pragma unroll
            for (int j = 0; j < 4; j++) { p[j] = __expf(accS[i][j] - mn); rs += p[j]; }
#pragma unroll
            for (int off = 8; off; off >>= 1) rs += __shfl_xor_sync(0xffffffffu, rs, off);
            l[i] = l[i] * corr + rs;
            m[i] = mn;
#pragma unroll
            for (int c = 0; c < 8; c++) accO[i][c] *= corr;
#pragma unroll
            for (int j = 0; j < 4; j++) Pt[(tx * 4 + j) * QT_PITCH + ty * 4 + i] = p[j];
        }
        __syncthreads();

#pragma unroll 4
        for (int j = 0; j < 64; j++) {
            float4 p4 = *(const float4*)&Pt[j * QT_PITCH + ty * 4];
            float4 v0 = *(const float4*)&Vs[j * 128 + tx * 8];
            float4 v1 = *(const float4*)&Vs[j * 128 + tx * 8 + 4];
            float pp[4] = {p4.x, p4.y, p4.z, p4.w};
            float vv[8] = {v0.x, v0.y, v0.z, v0.w, v1.x, v1.y, v1.z, v1.w};
#pragma unroll
            for (int i = 0; i < 4; i++)
#pragma unroll
                for (int c = 0; c < 8; c++) accO[i][c] += pp[i] * vv[c];
        }
    }

#pragma unroll
    for (int i = 0; i < 4; i++) {
        float invl = 1.0f / l[i];
        int row = qbase + ty * 4 + i;
        size_t off = ((size_t)(b * SS + row) * NHQ + h) * HD + tx * 8;
        __nv_bfloat162* oph = (__nv_bfloat162*)(oh + off);
        __nv_bfloat162* opl = (__nv_bfloat162*)(ol + off);
#pragma unroll
        for (int c = 0; c < 8; c += 2) {
            __nv_bfloat162 hh, ll;
            split_store2(accO[i][c] * invl, accO[i][c+1] * invl, &hh, &ll);
            oph[c >> 1] = hh;
            opl[c >> 1] = ll;
        }
    }
}

// ======================= SiLU * up (bf16-split output) =======================
__global__ void silu_mul_kernel(const float* __restrict__ gu,
                                __nv_bfloat16* __restrict__ ah, __nv_bfloat16* __restrict__ al)
{
    size_t idx = (size_t)blockIdx.x * blockDim.x + threadIdx.x;  // over TT*(INTER/4)
    size_t t = idx >> 11;
    size_t c = idx & 2047;
    const float4 g = *(const float4*)(gu + t * (2 * INTER) + c * 4);
    const float4 u = *(const float4*)(gu + t * (2 * INTER) + INTER + c * 4);
    float r0 = g.x / (1.f + __expf(-g.x)) * u.x;
    float r1 = g.y / (1.f + __expf(-g.y)) * u.y;
    float r2 = g.z / (1.f + __expf(-g.z)) * u.z;
    float r3 = g.w / (1.f + __expf(-g.w)) * u.w;
    __nv_bfloat162 h0, l0, h1, l1;
    split_store2(r0, r1, &h0, &l0);
    split_store2(r2, r3, &h1, &l1);
    __nv_bfloat162* ph = (__nv_bfloat162*)(ah + t * INTER + c * 4);
    __nv_bfloat162* pl = (__nv_bfloat162*)(al + t * INTER + c * 4);
    ph[0] = h0; ph[1] = h1;
    pl[0] = l0; pl[1] = l1;
}

// ======================= launch =======================
extern "C" void kernel_launch(void* const* d_in, const int* in_sizes, int n_in,
                              void* d_out, int out_size)
{
    const int*   positions = (const int*)  d_in[0];
    const float* hidden    = (const float*)d_in[1];
    const float* residual  = (const float*)d_in[2];
    const float* ln1       = (const float*)d_in[3];
    const float* ln2       = (const float*)d_in[4];
    const float* wq        = (const float*)d_in[5];
    const float* bq        = (const float*)d_in[6];
    const float* wk        = (const float*)d_in[7];
    const float* bk        = (const float*)d_in[8];
    const float* wv        = (const float*)d_in[9];
    const float* bv        = (const float*)d_in[10];
    const float* wo        = (const float*)d_in[11];
    const float* wgu       = (const float*)d_in[12];
    const float* wd        = (const float*)d_in[13];

    float* out_h   = (float*)d_out;
    float* out_res = out_h + (size_t)out_size / 2;

    float *res1, *q, *k, *v, *hattn, *gu;
    __nv_bfloat16 *xn_h, *xn_l, *at_h, *at_l, *h2_h, *h2_l, *ac_h, *ac_l;
    __nv_bfloat16 *wqT_h, *wqT_l, *wkT_h, *wkT_l, *wvT_h, *wvT_l;
    __nv_bfloat16 *woT_h, *woT_l, *guT_h, *guT_l, *wdT_h, *wdT_l;
    cudaGetSymbolAddress((void**)&res1,  g_res1);
    cudaGetSymbolAddress((void**)&q,     g_q);
    cudaGetSymbolAddress((void**)&k,     g_k);
    cudaGetSymbolAddress((void**)&v,     g_v);
    cudaGetSymbolAddress((void**)&hattn, g_hattn);
    cudaGetSymbolAddress((void**)&gu,    g_gu);
    cudaGetSymbolAddress((void**)&xn_h,  g_xn_h);
    cudaGetSymbolAddress((void**)&xn_l,  g_xn_l);
    cudaGetSymbolAddress((void**)&at_h,  g_at_h);
    cudaGetSymbolAddress((void**)&at_l,  g_at_l);
    cudaGetSymbolAddress((void**)&h2_h,  g_h2_h);
    cudaGetSymbolAddress((void**)&h2_l,  g_h2_l);
    cudaGetSymbolAddress((void**)&ac_h,  g_ac_h);
    cudaGetSymbolAddress((void**)&ac_l,  g_ac_l);
    cudaGetSymbolAddress((void**)&wqT_h, g_wqT_h);
    cudaGetSymbolAddress((void**)&wqT_l, g_wqT_l);
    cudaGetSymbolAddress((void**)&wkT_h, g_wkT_h);
    cudaGetSymbolAddress((void**)&wkT_l, g_wkT_l);
    cudaGetSymbolAddress((void**)&wvT_h, g_wvT_h);
    cudaGetSymbolAddress((void**)&wvT_l, g_wvT_l);
    cudaGetSymbolAddress((void**)&woT_h, g_woT_h);
    cudaGetSymbolAddress((void**)&woT_l, g_woT_l);
    cudaGetSymbolAddress((void**)&guT_h, g_guT_h);
    cudaGetSymbolAddress((void**)&guT_l, g_guT_l);
    cudaGetSymbolAddress((void**)&wdT_h, g_wdT_h);
    cudaGetSymbolAddress((void**)&wdT_l, g_wdT_l);

    cudaFuncSetAttribute(gemm_mma, cudaFuncAttributeMaxDynamicSharedMemorySize, GEMM_SMEM);
    cudaFuncSetAttribute(flash_kernel, cudaFuncAttributeMaxDynamicSharedMemorySize, FLASH_SMEM);

    // 0. weight transpose + bf16 split
    wsplit_kernel<<<dim3((NHQ*HD)/32, HH/32), dim3(32,8)>>>(wq, wqT_h, wqT_l, HH, NHQ*HD);
    wsplit_kernel<<<dim3((NKV*HD)/32, HH/32), dim3(32,8)>>>(wk, wkT_h, wkT_l, HH, NKV*HD);
    wsplit_kernel<<<dim3((NKV*HD)/32, HH/32), dim3(32,8)>>>(wv, wvT_h, wvT_l, HH, NKV*HD);
    wsplit_kernel<<<dim3(HH/32, (NHQ*HD)/32), dim3(32,8)>>>(wo, woT_h, woT_l, NHQ*HD, HH);
    wsplit_kernel<<<dim3((2*INTER)/32, HH/32), dim3(32,8)>>>(wgu, guT_h, guT_l, HH, 2*INTER);
    wsplit_kernel<<<dim3(HH/32, INTER/32), dim3(32,8)>>>(wd, wdT_h, wdT_l, INTER, HH);

    // 1. res1 = hidden + residual ; xn = rmsnorm(res1)*ln1 (bf16 split)
    add_rmsnorm_kernel<<<TT, 256>>>(hidden, residual, ln1, res1, xn_h, xn_l);

    // 2. QKV projections (tensor cores via mma.sync)
    gemm_mma<<<dim3((NHQ*HD)/128, TT/128), 256, GEMM_SMEM>>>(xn_h, xn_l, wqT_h, wqT_l, bq, q, TT, NHQ*HD, HH);
    gemm_mma<<<dim3((NKV*HD)/128, TT/128), 256, GEMM_SMEM>>>(xn_h, xn_l, wkT_h, wkT_l, bk, k, TT, NKV*HD, HH);
    gemm_mma<<<dim3((NKV*HD)/128, TT/128), 256, GEMM_SMEM>>>(xn_h, xn_l, wvT_h, wvT_l, bv, v, TT, NKV*HD, HH);

    // 3. RoPE
    init_freq_kernel<<<1, 64>>>();
    {
        int total = TT * (NHQ + NKV) * 64;
        rope_kernel<<<(total + 255) / 256, 256>>>(q, k, positions);
    }

    // 4. causal flash attention -> bf16 split
    flash_kernel<<<dim3(SS / 64, NHQ, BB), 256, FLASH_SMEM>>>(q, k, v, at_h, at_l);

    // 5. output projection
    gemm_mma<<<dim3(HH/128, TT/128), 256, GEMM_SMEM>>>(at_h, at_l, woT_h, woT_l, nullptr, hattn, TT, HH, NHQ*HD);

    // 6. res2 = hattn + res1 (-> out second half) ; h2 = rmsnorm(res2)*ln2 (bf16 split)
    add_rmsnorm_kernel<<<TT, 256>>>(hattn, res1, ln2, out_res, h2_h, h2_l);

    // 7. gate_up GEMM
    gemm_mma<<<dim3((2*INTER)/128, TT/128), 256, GEMM_SMEM>>>(h2_h, h2_l, guT_h, guT_l, nullptr, gu, TT, 2*INTER, HH);

    // 8. SiLU * up -> bf16 split
    {
        size_t total4 = (size_t)TT * (INTER / 4);
        silu_mul_kernel<<<(unsigned)(total4 / 256), 256>>>(gu, ac_h, ac_l);
    }

    // 9. down GEMM -> out first half
    gemm_mma<<<dim3(HH/128, TT/128), 256, GEMM_SMEM>>>(ac_h, ac_l, wdT_h, wdT_l, nullptr, out_h, TT, HH, INTER);
}